// round 10
// baseline (speedup 1.0000x reference)
#include <cuda_runtime.h>
#include <math.h>

#define RES_UP 0.05f
#define RES_DN 0.02f
#define REQ_UP 0.02f
#define REQ_DN 0.02f

#define MAXG 64

typedef unsigned long long u64;

// ---------- packed f32x2 helpers (sm_100+), u64-primary ----------
__device__ __forceinline__ u64 pk(float lo, float hi) {
    u64 r; asm("mov.b64 %0, {%1,%2};" : "=l"(r) : "f"(lo), "f"(hi)); return r;
}
__device__ __forceinline__ void upk(u64 p, float& lo, float& hi) {
    asm("mov.b64 {%0,%1}, %2;" : "=f"(lo), "=f"(hi) : "l"(p));
}
__device__ __forceinline__ u64 f2add(u64 a, u64 b) {
    u64 r; asm("add.rn.f32x2 %0, %1, %2;" : "=l"(r) : "l"(a), "l"(b)); return r;
}
__device__ __forceinline__ u64 f2fma(u64 a, u64 b, u64 c) {
    u64 r; asm("fma.rn.f32x2 %0, %1, %2, %3;" : "=l"(r) : "l"(a), "l"(b), "l"(c)); return r;
}
__device__ __forceinline__ u64 f2sub(u64 a, u64 b) {
    const u64 N1 = 0xBF800000BF800000ULL;  // (-1.0f, -1.0f)
    return f2fma(b, N1, a);                // a - b (exact)
}
// relu both halves in ONE asm block (keeps pair locality for the allocator)
__device__ __forceinline__ u64 f2relu(u64 a) {
    u64 r;
    asm("{\n\t.reg .f32 lo, hi;\n\t"
        "mov.b64 {lo,hi}, %1;\n\t"
        "max.f32 lo, lo, 0f00000000;\n\t"
        "max.f32 hi, hi, 0f00000000;\n\t"
        "mov.b64 %0, {lo,hi};\n\t}"
        : "=l"(r) : "l"(a));
    return r;
}

// Fused: one block per batch element; each 16-lane group owns one LP
// (timestep); 2 LPs per warp; 4 gen slots/lane = 2 packed pairs (u64).
// Pair p: lo gen = 32p+gl, hi gen = 32p+16+gl. Dead gens (g>=G) use poisoned
// constants (b=1e30, pmax=pmin=0) which pin their state at exactly 0.
__global__ __launch_bounds__(512) void pdhg_fused_kernel(
    const float* __restrict__ forecast, const float* __restrict__ pminv,
    const float* __restrict__ pmaxv, const float* __restrict__ bv,
    const float* __restrict__ cv, const int* __restrict__ nitp,
    float* __restrict__ out, int G, int B, int T, float tau)
{
    __shared__ float sobj[32];
    const int bb   = blockIdx.x;
    const int w    = threadIdx.x >> 5;
    const int grp  = (threadIdx.x >> 4) & 1;
    const int gl   = threadIdx.x & 15;
    const int t    = 2 * w + grp;
    const bool live = t < T;
    const int tc   = live ? t : T - 1;
    const float D  = forecast[bb * T + tc];
    const int nit  = *nitp;
    const float sig = tau;

    u64 tb[2], tcu[2], tcd[2], spx[2], spn[2];
#pragma unroll
    for (int p = 0; p < 2; ++p) {
        int glo = 32 * p + gl, ghi = glo + 16;
        float blo  = (glo < G) ? bv[glo]    : 1e30f;
        float bhi  = (ghi < G) ? bv[ghi]    : 1e30f;
        float pxlo = (glo < G) ? pmaxv[glo] : 0.f;
        float pxhi = (ghi < G) ? pmaxv[ghi] : 0.f;
        float pnlo = (glo < G) ? pminv[glo] : 0.f;
        float pnhi = (ghi < G) ? pminv[ghi] : 0.f;
        tb[p]  = pk(tau * blo,          tau * bhi);
        tcu[p] = pk(tau * RES_UP * blo, tau * RES_UP * bhi);
        tcd[p] = pk(tau * RES_DN * blo, tau * RES_DN * bhi);
        spx[p] = pk(sig * pxlo,         sig * pxhi);
        spn[p] = pk(sig * pnlo,         sig * pnhi);
    }
    const u64 NTAU = pk(-tau, -tau);
    const u64 SIGp = pk(sig, sig);
    const u64 NSIG = pk(-sig, -sig);
    const float ruD = REQ_UP * D, rdD = REQ_DN * D;

    // packed state
    u64 P[2]  = {0, 0}, Ru[2] = {0, 0}, Rd[2] = {0, 0};
    u64 av[2] = {0, 0}, dv[2] = {0, 0}, uv[2] = {0, 0}, lv[2] = {0, 0};
    float y0 = 0.f, yu = 0.f, yd = 0.f;

#pragma unroll 2
    for (int it = 0; it < nit; ++it) {
        u64 ty0p = pk(tau * y0, tau * y0);
        u64 tyup = pk(tau * yu, tau * yu);
        u64 tydp = pk(tau * yd, tau * yd);
        u64 Pb[2], Rub[2], Rdb[2];
#pragma unroll
        for (int p = 0; p < 2; ++p) {
            // x_new = relu(x - tau*(c_obj + K^T y))
            u64 t1 = f2sub(av[p], dv[p]);
            u64 t2 = f2sub(uv[p], lv[p]);
            u64 t3 = f2add(t1, t2);
            u64 e  = f2sub(P[p], tb[p]);
            e = f2sub(e, ty0p);
            e = f2fma(NTAU, t3, e);
            u64 Pn = f2relu(e);

            e = f2sub(Ru[p], tcu[p]);
            e = f2fma(NTAU, av[p], e);
            e = f2add(e, tyup);
            u64 Run = f2relu(e);

            e = f2sub(Rd[p], tcd[p]);
            e = f2fma(NTAU, dv[p], e);
            e = f2add(e, tydp);
            u64 Rdn = f2relu(e);

            // x_bar = 2*x_new - x_old
            Pb[p]  = f2sub(f2add(Pn, Pn),   P[p]);
            Rub[p] = f2sub(f2add(Run, Run), Ru[p]);
            Rdb[p] = f2sub(f2add(Rdn, Rdn), Rd[p]);
            P[p] = Pn; Ru[p] = Run; Rd[p] = Rdn;
        }

        // lane-local partial sums
        float sP, sRu, sRd;
        { u64 s = f2add(Pb[0],  Pb[1]);  float x, y; upk(s, x, y); sP  = x + y; }
        { u64 s = f2add(Rub[0], Rub[1]); float x, y; upk(s, x, y); sRu = x + y; }
        { u64 s = f2add(Rdb[0], Rdb[1]); float x, y; upk(s, x, y); sRd = x + y; }

        // 4-stage butterfly over the 16-lane group; dual updates (independent
        // of the sums) interleaved to fill SHFL latency.
        sP  += __shfl_xor_sync(0xffffffffu, sP,  8);
        sRu += __shfl_xor_sync(0xffffffffu, sRu, 8);
        sRd += __shfl_xor_sync(0xffffffffu, sRd, 8);
        {   // pair 0: a, d
            u64 q = f2add(Pb[0], Rub[0]);
            av[0] = f2relu(f2fma(SIGp, q, f2sub(av[0], spx[0])));
            q = f2sub(Rdb[0], Pb[0]);
            dv[0] = f2relu(f2fma(SIGp, q, f2add(dv[0], spn[0])));
        }
        sP  += __shfl_xor_sync(0xffffffffu, sP,  4);
        sRu += __shfl_xor_sync(0xffffffffu, sRu, 4);
        sRd += __shfl_xor_sync(0xffffffffu, sRd, 4);
        {   // pair 0: u, l
            uv[0] = f2relu(f2fma(SIGp, Pb[0], f2sub(uv[0], spx[0])));
            lv[0] = f2relu(f2fma(NSIG, Pb[0], f2add(lv[0], spn[0])));
        }
        sP  += __shfl_xor_sync(0xffffffffu, sP,  2);
        sRu += __shfl_xor_sync(0xffffffffu, sRu, 2);
        sRd += __shfl_xor_sync(0xffffffffu, sRd, 2);
        {   // pair 1: a, d
            u64 q = f2add(Pb[1], Rub[1]);
            av[1] = f2relu(f2fma(SIGp, q, f2sub(av[1], spx[1])));
            q = f2sub(Rdb[1], Pb[1]);
            dv[1] = f2relu(f2fma(SIGp, q, f2add(dv[1], spn[1])));
        }
        sP  += __shfl_xor_sync(0xffffffffu, sP,  1);
        sRu += __shfl_xor_sync(0xffffffffu, sRu, 1);
        sRd += __shfl_xor_sync(0xffffffffu, sRd, 1);
        {   // pair 1: u, l
            uv[1] = f2relu(f2fma(SIGp, Pb[1], f2sub(uv[1], spx[1])));
            lv[1] = f2relu(f2fma(NSIG, Pb[1], f2add(lv[1], spn[1])));
        }

        // scalar dual rows
        y0 = fmaf(sig, sP - D, y0);
        yu = fmaxf(fmaf(sig, ruD - sRu, yu), 0.f);
        yd = fmaxf(fmaf(sig, rdD - sRd, yd), 0.f);
    }

    // outputs: P_DA | R_up | R_dn | obj | Cost_DA, all (B, G, T)
    size_t BGT = (size_t)B * G * T;
    float* Pout = out;
    float* Ruo  = out + BGT;
    float* Rdo  = out + 2 * BGT;
    float* Co   = out + 3 * BGT + B;

    float part = 0.f;
    if (live) {
#pragma unroll
        for (int p = 0; p < 2; ++p) {
            float Plo, Phi, Rulo, Ruhi, Rdlo, Rdhi;
            upk(P[p], Plo, Phi);
            upk(Ru[p], Rulo, Ruhi);
            upk(Rd[p], Rdlo, Rdhi);
            int glo = 32 * p + gl, ghi = glo + 16;
            if (glo < G) {
                size_t i = ((size_t)bb * G + glo) * T + t;
                float bg = bv[glo];
                float co = fmaf(bg, Plo, cv[glo]);
                Pout[i] = Plo; Ruo[i] = Rulo; Rdo[i] = Rdlo; Co[i] = co;
                part += co + RES_UP * bg * Rulo + RES_DN * bg * Rdlo;
            }
            if (ghi < G) {
                size_t i = ((size_t)bb * G + ghi) * T + t;
                float bg = bv[ghi];
                float co = fmaf(bg, Phi, cv[ghi]);
                Pout[i] = Phi; Ruo[i] = Ruhi; Rdo[i] = Rdhi; Co[i] = co;
                part += co + RES_UP * bg * Ruhi + RES_DN * bg * Rdhi;
            }
        }
    }
#pragma unroll
    for (int k = 8; k > 0; k >>= 1)
        part += __shfl_xor_sync(0xffffffffu, part, k);
    if (live && gl == 0) sobj[t] = part;
    __syncthreads();

    // block reduction of T per-LP partials -> obj[bb] (warp 0)
    if (w == 0) {
        int lane = threadIdx.x & 31;
        float v = (lane < T) ? sobj[lane] : 0.f;
#pragma unroll
        for (int k = 16; k > 0; k >>= 1)
            v += __shfl_xor_sync(0xffffffffu, v, k);
        if (lane == 0) out[3 * BGT + bb] = v;
    }
}

// ---------------- host: structured spectral norm of K (power iteration) -----
static void K_matvec(const double* v, double* w, int G) {
    int n1 = G, n2 = 2 * G;
    double s0 = 0, s1 = 0, s2 = 0;
    for (int g = 0; g < G; ++g) { s0 += v[g]; s1 += v[n1 + g]; s2 += v[n2 + g]; }
    w[0] = s0;
    for (int g = 0; g < G; ++g) {
        w[1 + g]          =  v[g] + v[n1 + g];
        w[1 + G + g]      = -v[g] + v[n2 + g];
        w[1 + 2 * G + g]  =  v[g];
        w[1 + 3 * G + g]  = -v[g];
    }
    w[1 + 4 * G]     = -s1;
    w[1 + 4 * G + 1] = -s2;
}

static void KT_matvec(const double* w, double* z, int G) {
    double yu = w[1 + 4 * G], yd = w[1 + 4 * G + 1];
    for (int g = 0; g < G; ++g) {
        z[g]           = w[0] + w[1 + g] - w[1 + G + g] + w[1 + 2 * G + g] - w[1 + 3 * G + g];
        z[G + g]       = w[1 + g] - yu;
        z[2 * G + g]   = w[1 + G + g] - yd;
    }
}

static double spectral_norm_K(int G) {
    static double v[3 * MAXG], w[4 * MAXG + 3], z[3 * MAXG];
    int n = 3 * G;
    for (int i = 0; i < n; ++i) v[i] = 1.0 + 0.001 * (double)(i % 7);
    double lam = 1.0;
    for (int it = 0; it < 4000; ++it) {
        K_matvec(v, w, G);
        KT_matvec(w, z, G);
        double nrm = 0.0;
        for (int i = 0; i < n; ++i) nrm += z[i] * z[i];
        nrm = sqrt(nrm);
        lam = nrm;
        double inv = 1.0 / nrm;
        for (int i = 0; i < n; ++i) v[i] = z[i] * inv;
    }
    return sqrt(lam);  // sigma_max(K)
}

extern "C" void kernel_launch(void* const* d_in, const int* in_sizes, int n_in,
                              void* d_out, int out_size) {
    const float* forecast = (const float*)d_in[0];
    const float* pminv    = (const float*)d_in[1];
    const float* pmaxv    = (const float*)d_in[2];
    const float* bv       = (const float*)d_in[3];
    const float* cv       = (const float*)d_in[4];
    const int*   nitp     = (const int*)d_in[5];

    int G  = in_sizes[1];
    int BT = in_sizes[0];
    // out_size = 4*B*G*T + B  with  B*T = BT  ->  B = out_size - 4*G*BT
    int B = out_size - 4 * G * BT;
    if (B <= 0) B = 1;
    int T = BT / B;

    double L = spectral_norm_K(G);
    float tau = (float)(0.9 / L);

    float* out = (float*)d_out;
    int wpb = (T + 1) / 2;
    if (wpb > 16) wpb = 16;
    pdhg_fused_kernel<<<B, wpb * 32>>>(
        forecast, pminv, pmaxv, bv, cv, nitp, out, G, B, T, tau);
}

// round 11
// speedup vs baseline: 1.6956x; 1.6956x over previous
#include <cuda_runtime.h>
#include <math.h>

#define RES_UP 0.05f
#define RES_DN 0.02f
#define REQ_UP 0.02f
#define REQ_DN 0.02f

#define MAXG 64

// ---------- packed f32x2 helpers: floats in/out, pack inside asm ----------
// r = a*b + c   (elementwise on the pair)
__device__ __forceinline__ void F2FMA(float& r0, float& r1,
    float a0, float a1, float b0, float b1, float c0, float c1) {
    asm("{\n\t.reg .b64 ra, rb, rc;\n\t"
        "mov.b64 ra, {%2,%3};\n\tmov.b64 rb, {%4,%5};\n\tmov.b64 rc, {%6,%7};\n\t"
        "fma.rn.f32x2 rc, ra, rb, rc;\n\tmov.b64 {%0,%1}, rc;\n\t}"
        : "=f"(r0), "=f"(r1)
        : "f"(a0), "f"(a1), "f"(b0), "f"(b1), "f"(c0), "f"(c1));
}
// r = a + b
__device__ __forceinline__ void F2ADD(float& r0, float& r1,
    float a0, float a1, float b0, float b1) {
    asm("{\n\t.reg .b64 ra, rb;\n\t"
        "mov.b64 ra, {%2,%3};\n\tmov.b64 rb, {%4,%5};\n\t"
        "add.rn.f32x2 ra, ra, rb;\n\tmov.b64 {%0,%1}, ra;\n\t}"
        : "=f"(r0), "=f"(r1)
        : "f"(a0), "f"(a1), "f"(b0), "f"(b1));
}
// r = a - b  (exact: fma(b,-1,a))
#define F2SUB(r0, r1, a0, a1, b0, b1) F2FMA(r0, r1, b0, b1, -1.f, -1.f, a0, a1)

// Fused: one block per batch element b. ceil(T/2) warps; each 16-lane group
// owns one LP (timestep). 4 gen slots/lane (g = 16*s + gl). Dead gens (g>=G)
// use poisoned constants (b=1e30, pmax=pmin=0) which pin their state at 0.
// Scalar dual rows are stored tau-scaled: m0 = -tau*y0, wu = tau*yu,
// wd = tau*yd (saves the per-iteration tau* premultiplies).
__global__ __launch_bounds__(512) void pdhg_fused_kernel(
    const float* __restrict__ forecast, const float* __restrict__ pminv,
    const float* __restrict__ pmaxv, const float* __restrict__ bv,
    const float* __restrict__ cv, const int* __restrict__ nitp,
    float* __restrict__ out, int G, int B, int T, float tau)
{
    __shared__ float sobj[64];
    const int bb   = blockIdx.x;
    const int w    = threadIdx.x >> 5;
    const int grp  = (threadIdx.x >> 4) & 1;
    const int gl   = threadIdx.x & 15;
    const int t    = 2 * w + grp;
    const bool live = t < T;
    const int tc   = live ? t : T - 1;
    const float D  = forecast[bb * T + tc];
    const int nit  = *nitp;
    const float sig = tau;
    const float ntau = -tau, nsig = -sig;
    const float tausig = tau * sig;          // tau^2
    const float ntausig = -tausig;
    const float sruD = tausig * (REQ_UP * D);
    const float srdD = tausig * (REQ_DN * D);

    float tb[4], tcu[4], tcd[4], spx[4], spn[4];
#pragma unroll
    for (int s = 0; s < 4; ++s) {
        int g = 16 * s + gl;
        float bg = (g < G) ? bv[g]    : 1e30f;
        float px = (g < G) ? pmaxv[g] : 0.f;
        float pn = (g < G) ? pminv[g] : 0.f;
        tb[s]  = tau * bg;
        tcu[s] = tau * RES_UP * bg;
        tcd[s] = tau * RES_DN * bg;
        spx[s] = sig * px;
        spn[s] = sig * pn;
    }

    // state
    float P[4]  = {0,0,0,0}, Ru[4] = {0,0,0,0}, Rd[4] = {0,0,0,0};
    float av[4] = {0,0,0,0}, dv[4] = {0,0,0,0}, uv[4] = {0,0,0,0}, lv[4] = {0,0,0,0};
    float m0 = 0.f, wu = 0.f, wd = 0.f;   // -tau*y0, tau*yu, tau*yd

#pragma unroll 2
    for (int it = 0; it < nit; ++it) {
        float Pb[4], Rub[4], Rdb[4];
#pragma unroll
        for (int q = 0; q < 2; ++q) {
            const int i = 2 * q, j = i + 1;
            float t0, t1, s0, s1, e0, e1;
            // t = a - d + u - l
            F2SUB(t0, t1, av[i], av[j], dv[i], dv[j]);
            F2SUB(s0, s1, uv[i], uv[j], lv[i], lv[j]);
            F2ADD(t0, t1, t0, t1, s0, s1);
            // P_new = relu(P - tau*b + m0 - tau*t)
            F2SUB(e0, e1, P[i], P[j], tb[i], tb[j]);
            F2ADD(e0, e1, e0, e1, m0, m0);
            F2FMA(e0, e1, t0, t1, ntau, ntau, e0, e1);
            float Pn0 = fmaxf(e0, 0.f), Pn1 = fmaxf(e1, 0.f);
            // Ru_new = relu(Ru - tau*cu - tau*a + wu)
            F2SUB(e0, e1, Ru[i], Ru[j], tcu[i], tcu[j]);
            F2ADD(e0, e1, e0, e1, wu, wu);
            F2FMA(e0, e1, av[i], av[j], ntau, ntau, e0, e1);
            float Run0 = fmaxf(e0, 0.f), Run1 = fmaxf(e1, 0.f);
            // Rd_new = relu(Rd - tau*cd - tau*d + wd)
            F2SUB(e0, e1, Rd[i], Rd[j], tcd[i], tcd[j]);
            F2ADD(e0, e1, e0, e1, wd, wd);
            F2FMA(e0, e1, dv[i], dv[j], ntau, ntau, e0, e1);
            float Rdn0 = fmaxf(e0, 0.f), Rdn1 = fmaxf(e1, 0.f);
            // x_bar = 2*x_new - x_old
            F2ADD(e0, e1, Pn0, Pn1, Pn0, Pn1);
            F2SUB(Pb[i], Pb[j], e0, e1, P[i], P[j]);
            F2ADD(e0, e1, Run0, Run1, Run0, Run1);
            F2SUB(Rub[i], Rub[j], e0, e1, Ru[i], Ru[j]);
            F2ADD(e0, e1, Rdn0, Rdn1, Rdn0, Rdn1);
            F2SUB(Rdb[i], Rdb[j], e0, e1, Rd[i], Rd[j]);
            P[i] = Pn0; P[j] = Pn1; Ru[i] = Run0; Ru[j] = Run1; Rd[i] = Rdn0; Rd[j] = Rdn1;
        }

        // lane-local partial sums
        float sP, sRu, sRd, h0, h1;
        F2ADD(h0, h1, Pb[0], Pb[1], Pb[2], Pb[3]);     sP  = h0 + h1;
        F2ADD(h0, h1, Rub[0], Rub[1], Rub[2], Rub[3]); sRu = h0 + h1;
        F2ADD(h0, h1, Rdb[0], Rdb[1], Rdb[2], Rdb[3]); sRd = h0 + h1;

        // 4-stage butterfly over the 16-lane group; dual updates interleaved.
        sP  += __shfl_xor_sync(0xffffffffu, sP,  8);
        sRu += __shfl_xor_sync(0xffffffffu, sRu, 8);
        sRd += __shfl_xor_sync(0xffffffffu, sRd, 8);
        {   // pair 0: a, d
            float t0, t1, e0, e1;
            F2ADD(t0, t1, Pb[0], Pb[1], Rub[0], Rub[1]);
            F2SUB(e0, e1, av[0], av[1], spx[0], spx[1]);
            F2FMA(e0, e1, t0, t1, sig, sig, e0, e1);
            av[0] = fmaxf(e0, 0.f); av[1] = fmaxf(e1, 0.f);
            F2SUB(t0, t1, Rdb[0], Rdb[1], Pb[0], Pb[1]);
            F2ADD(e0, e1, dv[0], dv[1], spn[0], spn[1]);
            F2FMA(e0, e1, t0, t1, sig, sig, e0, e1);
            dv[0] = fmaxf(e0, 0.f); dv[1] = fmaxf(e1, 0.f);
        }
        sP  += __shfl_xor_sync(0xffffffffu, sP,  4);
        sRu += __shfl_xor_sync(0xffffffffu, sRu, 4);
        sRd += __shfl_xor_sync(0xffffffffu, sRd, 4);
        {   // pair 0: u, l
            float e0, e1;
            F2SUB(e0, e1, uv[0], uv[1], spx[0], spx[1]);
            F2FMA(e0, e1, Pb[0], Pb[1], sig, sig, e0, e1);
            uv[0] = fmaxf(e0, 0.f); uv[1] = fmaxf(e1, 0.f);
            F2ADD(e0, e1, lv[0], lv[1], spn[0], spn[1]);
            F2FMA(e0, e1, Pb[0], Pb[1], nsig, nsig, e0, e1);
            lv[0] = fmaxf(e0, 0.f); lv[1] = fmaxf(e1, 0.f);
        }
        sP  += __shfl_xor_sync(0xffffffffu, sP,  2);
        sRu += __shfl_xor_sync(0xffffffffu, sRu, 2);
        sRd += __shfl_xor_sync(0xffffffffu, sRd, 2);
        {   // pair 1: a, d
            float t0, t1, e0, e1;
            F2ADD(t0, t1, Pb[2], Pb[3], Rub[2], Rub[3]);
            F2SUB(e0, e1, av[2], av[3], spx[2], spx[3]);
            F2FMA(e0, e1, t0, t1, sig, sig, e0, e1);
            av[2] = fmaxf(e0, 0.f); av[3] = fmaxf(e1, 0.f);
            F2SUB(t0, t1, Rdb[2], Rdb[3], Pb[2], Pb[3]);
            F2ADD(e0, e1, dv[2], dv[3], spn[2], spn[3]);
            F2FMA(e0, e1, t0, t1, sig, sig, e0, e1);
            dv[2] = fmaxf(e0, 0.f); dv[3] = fmaxf(e1, 0.f);
        }
        sP  += __shfl_xor_sync(0xffffffffu, sP,  1);
        sRu += __shfl_xor_sync(0xffffffffu, sRu, 1);
        sRd += __shfl_xor_sync(0xffffffffu, sRd, 1);
        {   // pair 1: u, l
            float e0, e1;
            F2SUB(e0, e1, uv[2], uv[3], spx[2], spx[3]);
            F2FMA(e0, e1, Pb[2], Pb[3], sig, sig, e0, e1);
            uv[2] = fmaxf(e0, 0.f); uv[3] = fmaxf(e1, 0.f);
            F2ADD(e0, e1, lv[2], lv[3], spn[2], spn[3]);
            F2FMA(e0, e1, Pb[2], Pb[3], nsig, nsig, e0, e1);
            lv[2] = fmaxf(e0, 0.f); lv[3] = fmaxf(e1, 0.f);
        }

        // tau-scaled scalar rows:
        // m0 = -tau*y0:  y0 += sig*(sP - D)      ->  m0 -= tausig*(sP - D)
        // wu = tau*yu:   yu = max(yu + sig*(ruD - sRu), 0)
        //                -> wu = max(wu + tausig*ruD - tausig*sRu, 0)
        m0 = fmaf(ntausig, sP - D, m0);
        wu = fmaxf(fmaf(ntausig, sRu, wu + sruD), 0.f);
        wd = fmaxf(fmaf(ntausig, sRd, wd + srdD), 0.f);
    }

    // outputs: P_DA | R_up | R_dn | obj | Cost_DA, all (B, G, T)
    size_t BGT = (size_t)B * G * T;
    float* Pout = out;
    float* Ruo  = out + BGT;
    float* Rdo  = out + 2 * BGT;
    float* Co   = out + 3 * BGT + B;

    float part = 0.f;
    if (live) {
#pragma unroll
        for (int s = 0; s < 4; ++s) {
            int g = 16 * s + gl;
            if (g < G) {
                size_t i = ((size_t)bb * G + g) * T + t;
                float bg = bv[g];
                float co = fmaf(bg, P[s], cv[g]);
                Pout[i] = P[s]; Ruo[i] = Ru[s]; Rdo[i] = Rd[s]; Co[i] = co;
                part += co + RES_UP * bg * Ru[s] + RES_DN * bg * Rd[s];
            }
        }
    }
#pragma unroll
    for (int k = 8; k > 0; k >>= 1)
        part += __shfl_xor_sync(0xffffffffu, part, k);
    if (live && gl == 0) sobj[t] = part;
    __syncthreads();

    // block reduction of T per-LP partials -> obj[bb] (warp 0 only)
    if (w == 0) {
        int lane = threadIdx.x & 31;
        float v = (lane < T) ? sobj[lane] : 0.f;
        if (32 + lane < T) v += sobj[32 + lane];
#pragma unroll
        for (int k = 16; k > 0; k >>= 1)
            v += __shfl_xor_sync(0xffffffffu, v, k);
        if (lane == 0) out[3 * BGT + bb] = v;
    }
}

// ---------------- host: structured spectral norm of K (power iteration) -----
static void K_matvec(const double* v, double* w, int G) {
    int n1 = G, n2 = 2 * G;
    double s0 = 0, s1 = 0, s2 = 0;
    for (int g = 0; g < G; ++g) { s0 += v[g]; s1 += v[n1 + g]; s2 += v[n2 + g]; }
    w[0] = s0;
    for (int g = 0; g < G; ++g) {
        w[1 + g]          =  v[g] + v[n1 + g];
        w[1 + G + g]      = -v[g] + v[n2 + g];
        w[1 + 2 * G + g]  =  v[g];
        w[1 + 3 * G + g]  = -v[g];
    }
    w[1 + 4 * G]     = -s1;
    w[1 + 4 * G + 1] = -s2;
}

static void KT_matvec(const double* w, double* z, int G) {
    double yu = w[1 + 4 * G], yd = w[1 + 4 * G + 1];
    for (int g = 0; g < G; ++g) {
        z[g]           = w[0] + w[1 + g] - w[1 + G + g] + w[1 + 2 * G + g] - w[1 + 3 * G + g];
        z[G + g]       = w[1 + g] - yu;
        z[2 * G + g]   = w[1 + G + g] - yd;
    }
}

static double spectral_norm_K(int G) {
    static double v[3 * MAXG], w[4 * MAXG + 3], z[3 * MAXG];
    int n = 3 * G;
    for (int i = 0; i < n; ++i) v[i] = 1.0 + 0.001 * (double)(i % 7);
    double lam = 1.0;
    for (int it = 0; it < 4000; ++it) {
        K_matvec(v, w, G);
        KT_matvec(w, z, G);
        double nrm = 0.0;
        for (int i = 0; i < n; ++i) nrm += z[i] * z[i];
        nrm = sqrt(nrm);
        lam = nrm;
        double inv = 1.0 / nrm;
        for (int i = 0; i < n; ++i) v[i] = z[i] * inv;
    }
    return sqrt(lam);  // sigma_max(K)
}

extern "C" void kernel_launch(void* const* d_in, const int* in_sizes, int n_in,
                              void* d_out, int out_size) {
    const float* forecast = (const float*)d_in[0];
    const float* pminv    = (const float*)d_in[1];
    const float* pmaxv    = (const float*)d_in[2];
    const float* bv       = (const float*)d_in[3];
    const float* cv       = (const float*)d_in[4];
    const int*   nitp     = (const int*)d_in[5];

    int G  = in_sizes[1];
    int BT = in_sizes[0];
    // out_size = 4*B*G*T + B  with  B*T = BT  ->  B = out_size - 4*G*BT
    int B = out_size - 4 * G * BT;
    if (B <= 0) B = 1;
    int T = BT / B;

    double L = spectral_norm_K(G);
    float tau = (float)(0.9 / L);

    float* out = (float*)d_out;
    int wpb = (T + 1) / 2;              // warps per block (one per 2 timesteps)
    if (wpb > 16) wpb = 16;             // safety: T <= 32 assumed for block fit
    pdhg_fused_kernel<<<B, wpb * 32>>>(
        forecast, pminv, pmaxv, bv, cv, nitp, out, G, B, T, tau);
}

// round 13
// speedup vs baseline: 1.7367x; 1.0242x over previous
#include <cuda_runtime.h>
#include <math.h>

#define RES_UP 0.05f
#define RES_DN 0.02f
#define REQ_UP 0.02f
#define REQ_DN 0.02f

#define MAXG 64

// ---------- packed f32x2 helpers: floats in/out, pack inside asm ----------
// r = a*b + c   (elementwise on the pair)
__device__ __forceinline__ void F2FMA(float& r0, float& r1,
    float a0, float a1, float b0, float b1, float c0, float c1) {
    asm("{\n\t.reg .b64 ra, rb, rc;\n\t"
        "mov.b64 ra, {%2,%3};\n\tmov.b64 rb, {%4,%5};\n\tmov.b64 rc, {%6,%7};\n\t"
        "fma.rn.f32x2 rc, ra, rb, rc;\n\tmov.b64 {%0,%1}, rc;\n\t}"
        : "=f"(r0), "=f"(r1)
        : "f"(a0), "f"(a1), "f"(b0), "f"(b1), "f"(c0), "f"(c1));
}
// r = a + b
__device__ __forceinline__ void F2ADD(float& r0, float& r1,
    float a0, float a1, float b0, float b1) {
    asm("{\n\t.reg .b64 ra, rb;\n\t"
        "mov.b64 ra, {%2,%3};\n\tmov.b64 rb, {%4,%5};\n\t"
        "add.rn.f32x2 ra, ra, rb;\n\tmov.b64 {%0,%1}, ra;\n\t}"
        : "=f"(r0), "=f"(r1)
        : "f"(a0), "f"(a1), "f"(b0), "f"(b1));
}
// r = a - b  (exact: fma(b,-1,a))
#define F2SUB(r0, r1, a0, a1, b0, b1) F2FMA(r0, r1, b0, b1, -1.f, -1.f, a0, a1)

// Fused, software-pipelined PDHG. One block per batch element; each 16-lane
// group owns one LP (timestep); 4 gen slots/lane (g = 16*s + gl). Dead gens
// (g>=G) use poisoned constants (b=1e30, pmax=pmin=0) -> state pinned at 0.
//
// Pipeline: x^1 = relu(-tau*c) = 0 exactly, so the prologue is free
// (x = xbar = partials = 0). Each loop iteration k (k = 1..nit-1) does:
//   butterfly(xbar^{k-1})  [4 SHFL stages]
//   gaps: dual-vec update (y^k) and the scalar-free part of primal k
//   after last stage: scalar rows (m0,wu,wd = y^k scalars, tau-scaled),
//   then finish primal: +scalars, relu -> x^{k+1}, xbar^k, lane partials.
// The reference's final dual update (unused) is skipped.
__global__ __launch_bounds__(512) void pdhg_fused_kernel(
    const float* __restrict__ forecast, const float* __restrict__ pminv,
    const float* __restrict__ pmaxv, const float* __restrict__ bv,
    const float* __restrict__ cv, const int* __restrict__ nitp,
    float* __restrict__ out, int G, int B, int T, float tau)
{
    __shared__ float sobj[64];
    const int bb   = blockIdx.x;
    const int w    = threadIdx.x >> 5;
    const int grp  = (threadIdx.x >> 4) & 1;
    const int gl   = threadIdx.x & 15;
    const int t    = 2 * w + grp;
    const bool live = t < T;
    const int tc   = live ? t : T - 1;
    const float D  = forecast[bb * T + tc];
    const int nit  = *nitp;
    const float sig = tau;
    const float ntau = -tau, nsig = -sig;
    const float tausig = tau * sig;
    const float ntausig = -tausig;
    const float sruD = tausig * (REQ_UP * D);
    const float srdD = tausig * (REQ_DN * D);

    float tb[4], tcu[4], tcd[4], spx[4], spn[4];
#pragma unroll
    for (int s = 0; s < 4; ++s) {
        int g = 16 * s + gl;
        float bg = (g < G) ? bv[g]    : 1e30f;
        float px = (g < G) ? pmaxv[g] : 0.f;
        float pn = (g < G) ? pminv[g] : 0.f;
        tb[s]  = tau * bg;
        tcu[s] = tau * RES_UP * bg;
        tcd[s] = tau * RES_DN * bg;
        spx[s] = sig * px;
        spn[s] = sig * pn;
    }

    // state: x (P,Ru,Rd), per-gen duals, tau-scaled scalar duals,
    // carried xbar (Pb,Rub,Rdb) and carried lane partials (sP,sRu,sRd).
    float P[4]  = {0,0,0,0}, Ru[4] = {0,0,0,0}, Rd[4] = {0,0,0,0};
    float av[4] = {0,0,0,0}, dv[4] = {0,0,0,0}, uv[4] = {0,0,0,0}, lv[4] = {0,0,0,0};
    float Pb[4] = {0,0,0,0}, Rub[4] = {0,0,0,0}, Rdb[4] = {0,0,0,0};
    float m0 = 0.f, wu = 0.f, wd = 0.f;
    float sP = 0.f, sRu = 0.f, sRd = 0.f;

#pragma unroll 2
    for (int it = 1; it < nit; ++it) {
        float eP[4], eRu[4], eRd[4];

        // ---- butterfly stage 8 ----
        sP  += __shfl_xor_sync(0xffffffffu, sP,  8);
        sRu += __shfl_xor_sync(0xffffffffu, sRu, 8);
        sRd += __shfl_xor_sync(0xffffffffu, sRd, 8);
        // fill: a,d dual updates (both pairs) using xbar^{k-1}
#pragma unroll
        for (int q = 0; q < 2; ++q) {
            const int i = 2 * q, j = i + 1;
            float t0, t1, e0, e1;
            F2ADD(t0, t1, Pb[i], Pb[j], Rub[i], Rub[j]);
            F2SUB(e0, e1, av[i], av[j], spx[i], spx[j]);
            F2FMA(e0, e1, t0, t1, sig, sig, e0, e1);
            av[i] = fmaxf(e0, 0.f); av[j] = fmaxf(e1, 0.f);
            F2SUB(t0, t1, Rdb[i], Rdb[j], Pb[i], Pb[j]);
            F2ADD(e0, e1, dv[i], dv[j], spn[i], spn[j]);
            F2FMA(e0, e1, t0, t1, sig, sig, e0, e1);
            dv[i] = fmaxf(e0, 0.f); dv[j] = fmaxf(e1, 0.f);
        }

        // ---- butterfly stage 4 ----
        sP  += __shfl_xor_sync(0xffffffffu, sP,  4);
        sRu += __shfl_xor_sync(0xffffffffu, sRu, 4);
        sRd += __shfl_xor_sync(0xffffffffu, sRd, 4);
        // fill: u,l dual updates (both pairs)
#pragma unroll
        for (int q = 0; q < 2; ++q) {
            const int i = 2 * q, j = i + 1;
            float e0, e1;
            F2SUB(e0, e1, uv[i], uv[j], spx[i], spx[j]);
            F2FMA(e0, e1, Pb[i], Pb[j], sig, sig, e0, e1);
            uv[i] = fmaxf(e0, 0.f); uv[j] = fmaxf(e1, 0.f);
            F2ADD(e0, e1, lv[i], lv[j], spn[i], spn[j]);
            F2FMA(e0, e1, Pb[i], Pb[j], nsig, nsig, e0, e1);
            lv[i] = fmaxf(e0, 0.f); lv[j] = fmaxf(e1, 0.f);
        }

        // ---- butterfly stage 2 ----
        sP  += __shfl_xor_sync(0xffffffffu, sP,  2);
        sRu += __shfl_xor_sync(0xffffffffu, sRu, 2);
        sRd += __shfl_xor_sync(0xffffffffu, sRd, 2);
        // fill: scalar-free part of primal update k (uses NEW duals y^k)
#pragma unroll
        for (int q = 0; q < 2; ++q) {
            const int i = 2 * q, j = i + 1;
            float t0, t1, s0, s1;
            F2SUB(t0, t1, av[i], av[j], dv[i], dv[j]);
            F2SUB(s0, s1, uv[i], uv[j], lv[i], lv[j]);
            F2ADD(t0, t1, t0, t1, s0, s1);
            F2SUB(eP[i], eP[j], P[i], P[j], tb[i], tb[j]);
            F2FMA(eP[i], eP[j], t0, t1, ntau, ntau, eP[i], eP[j]);
            F2SUB(eRu[i], eRu[j], Ru[i], Ru[j], tcu[i], tcu[j]);
            F2FMA(eRu[i], eRu[j], av[i], av[j], ntau, ntau, eRu[i], eRu[j]);
            F2SUB(eRd[i], eRd[j], Rd[i], Rd[j], tcd[i], tcd[j]);
            F2FMA(eRd[i], eRd[j], dv[i], dv[j], ntau, ntau, eRd[i], eRd[j]);
        }

        // ---- butterfly stage 1 ----
        sP  += __shfl_xor_sync(0xffffffffu, sP,  1);
        sRu += __shfl_xor_sync(0xffffffffu, sRu, 1);
        sRd += __shfl_xor_sync(0xffffffffu, sRd, 1);

        // scalar dual rows (tau-scaled): y^k scalars
        m0 = fmaf(ntausig, sP - D, m0);
        wu = fmaxf(fmaf(ntausig, sRu, wu + sruD), 0.f);
        wd = fmaxf(fmaf(ntausig, sRd, wd + srdD), 0.f);

        // finish primal k: add scalars, relu -> x^{k+1}; xbar^k; partials
        float hP = 0.f, hRu = 0.f, hRd = 0.f;
#pragma unroll
        for (int q = 0; q < 2; ++q) {
            const int i = 2 * q, j = i + 1;
            float e0, e1;
            F2ADD(e0, e1, eP[i], eP[j], m0, m0);
            float Pn0 = fmaxf(e0, 0.f), Pn1 = fmaxf(e1, 0.f);
            F2ADD(e0, e1, eRu[i], eRu[j], wu, wu);
            float Run0 = fmaxf(e0, 0.f), Run1 = fmaxf(e1, 0.f);
            F2ADD(e0, e1, eRd[i], eRd[j], wd, wd);
            float Rdn0 = fmaxf(e0, 0.f), Rdn1 = fmaxf(e1, 0.f);
            F2ADD(e0, e1, Pn0, Pn1, Pn0, Pn1);
            F2SUB(Pb[i], Pb[j], e0, e1, P[i], P[j]);
            F2ADD(e0, e1, Run0, Run1, Run0, Run1);
            F2SUB(Rub[i], Rub[j], e0, e1, Ru[i], Ru[j]);
            F2ADD(e0, e1, Rdn0, Rdn1, Rdn0, Rdn1);
            F2SUB(Rdb[i], Rdb[j], e0, e1, Rd[i], Rd[j]);
            P[i] = Pn0; P[j] = Pn1; Ru[i] = Run0; Ru[j] = Run1; Rd[i] = Rdn0; Rd[j] = Rdn1;
        }
        {
            float h0, h1;
            F2ADD(h0, h1, Pb[0], Pb[1], Pb[2], Pb[3]);     hP  = h0 + h1;
            F2ADD(h0, h1, Rub[0], Rub[1], Rub[2], Rub[3]); hRu = h0 + h1;
            F2ADD(h0, h1, Rdb[0], Rdb[1], Rdb[2], Rdb[3]); hRd = h0 + h1;
        }
        sP = hP; sRu = hRu; sRd = hRd;
    }

    // outputs: P_DA | R_up | R_dn | obj | Cost_DA, all (B, G, T)
    size_t BGT = (size_t)B * G * T;
    float* Pout = out;
    float* Ruo  = out + BGT;
    float* Rdo  = out + 2 * BGT;
    float* Co   = out + 3 * BGT + B;

    float part = 0.f;
    if (live) {
#pragma unroll
        for (int s = 0; s < 4; ++s) {
            int g = 16 * s + gl;
            if (g < G) {
                size_t i = ((size_t)bb * G + g) * T + t;
                float bg = bv[g];
                float co = fmaf(bg, P[s], cv[g]);
                Pout[i] = P[s]; Ruo[i] = Ru[s]; Rdo[i] = Rd[s]; Co[i] = co;
                part += co + RES_UP * bg * Ru[s] + RES_DN * bg * Rd[s];
            }
        }
    }
#pragma unroll
    for (int k = 8; k > 0; k >>= 1)
        part += __shfl_xor_sync(0xffffffffu, part, k);
    if (live && gl == 0) sobj[t] = part;
    __syncthreads();

    // block reduction of T per-LP partials -> obj[bb] (warp 0 only)
    if (w == 0) {
        int lane = threadIdx.x & 31;
        float v = (lane < T) ? sobj[lane] : 0.f;
        if (32 + lane < T) v += sobj[32 + lane];
#pragma unroll
        for (int k = 16; k > 0; k >>= 1)
            v += __shfl_xor_sync(0xffffffffu, v, k);
        if (lane == 0) out[3 * BGT + bb] = v;
    }
}

// ---------------- host: structured spectral norm of K (power iteration) -----
static void K_matvec(const double* v, double* w, int G) {
    int n1 = G, n2 = 2 * G;
    double s0 = 0, s1 = 0, s2 = 0;
    for (int g = 0; g < G; ++g) { s0 += v[g]; s1 += v[n1 + g]; s2 += v[n2 + g]; }
    w[0] = s0;
    for (int g = 0; g < G; ++g) {
        w[1 + g]          =  v[g] + v[n1 + g];
        w[1 + G + g]      = -v[g] + v[n2 + g];
        w[1 + 2 * G + g]  =  v[g];
        w[1 + 3 * G + g]  = -v[g];
    }
    w[1 + 4 * G]     = -s1;
    w[1 + 4 * G + 1] = -s2;
}

static void KT_matvec(const double* w, double* z, int G) {
    double yu = w[1 + 4 * G], yd = w[1 + 4 * G + 1];
    for (int g = 0; g < G; ++g) {
        z[g]           = w[0] + w[1 + g] - w[1 + G + g] + w[1 + 2 * G + g] - w[1 + 3 * G + g];
        z[G + g]       = w[1 + g] - yu;
        z[2 * G + g]   = w[1 + G + g] - yd;
    }
}

static double spectral_norm_K(int G) {
    static double v[3 * MAXG], w[4 * MAXG + 3], z[3 * MAXG];
    int n = 3 * G;
    for (int i = 0; i < n; ++i) v[i] = 1.0 + 0.001 * (double)(i % 7);
    double lam = 1.0;
    for (int it = 0; it < 4000; ++it) {
        K_matvec(v, w, G);
        KT_matvec(w, z, G);
        double nrm = 0.0;
        for (int i = 0; i < n; ++i) nrm += z[i] * z[i];
        nrm = sqrt(nrm);
        lam = nrm;
        double inv = 1.0 / nrm;
        for (int i = 0; i < n; ++i) v[i] = z[i] * inv;
    }
    return sqrt(lam);  // sigma_max(K)
}

extern "C" void kernel_launch(void* const* d_in, const int* in_sizes, int n_in,
                              void* d_out, int out_size) {
    const float* forecast = (const float*)d_in[0];
    const float* pminv    = (const float*)d_in[1];
    const float* pmaxv    = (const float*)d_in[2];
    const float* bv       = (const float*)d_in[3];
    const float* cv       = (const float*)d_in[4];
    const int*   nitp     = (const int*)d_in[5];

    int G  = in_sizes[1];
    int BT = in_sizes[0];
    // out_size = 4*B*G*T + B  with  B*T = BT  ->  B = out_size - 4*G*BT
    int B = out_size - 4 * G * BT;
    if (B <= 0) B = 1;
    int T = BT / B;

    double L = spectral_norm_K(G);
    float tau = (float)(0.9 / L);

    float* out = (float*)d_out;
    int wpb = (T + 1) / 2;              // warps per block (one per 2 timesteps)
    if (wpb > 16) wpb = 16;             // safety: T <= 32 assumed for block fit
    pdhg_fused_kernel<<<B, wpb * 32>>>(
        forecast, pminv, pmaxv, bv, cv, nitp, out, G, B, T, tau);
}

// round 14
// speedup vs baseline: 1.8260x; 1.0514x over previous
#include <cuda_runtime.h>
#include <math.h>

#define RES_UP 0.05f
#define RES_DN 0.02f
#define REQ_UP 0.02f
#define REQ_DN 0.02f

#define MAXG 64

// ---------- packed f32x2 helpers: floats in/out, pack inside asm ----------
// r = a*b + c   (elementwise on the pair)
__device__ __forceinline__ void F2FMA(float& r0, float& r1,
    float a0, float a1, float b0, float b1, float c0, float c1) {
    asm("{\n\t.reg .b64 ra, rb, rc;\n\t"
        "mov.b64 ra, {%2,%3};\n\tmov.b64 rb, {%4,%5};\n\tmov.b64 rc, {%6,%7};\n\t"
        "fma.rn.f32x2 rc, ra, rb, rc;\n\tmov.b64 {%0,%1}, rc;\n\t}"
        : "=f"(r0), "=f"(r1)
        : "f"(a0), "f"(a1), "f"(b0), "f"(b1), "f"(c0), "f"(c1));
}
// r = a + b
__device__ __forceinline__ void F2ADD(float& r0, float& r1,
    float a0, float a1, float b0, float b1) {
    asm("{\n\t.reg .b64 ra, rb;\n\t"
        "mov.b64 ra, {%2,%3};\n\tmov.b64 rb, {%4,%5};\n\t"
        "add.rn.f32x2 ra, ra, rb;\n\tmov.b64 {%0,%1}, ra;\n\t}"
        : "=f"(r0), "=f"(r1)
        : "f"(a0), "f"(a1), "f"(b0), "f"(b1));
}
// r = a - b  (exact: fma(b,-1,a))
#define F2SUB(r0, r1, a0, a1, b0, b1) F2FMA(r0, r1, b0, b1, -1.f, -1.f, a0, a1)

// Fused, software-pipelined PDHG with DOUBLED primal state (X2 = 2x).
// relu(2e) = 2 relu(e) exactly, so the primal recurrence runs on X2 with
// pre-doubled constants; xbar = 2x_new - x_old = fma(X2_old, -0.5, X2_new)
// in ONE op (bitwise identical to the 2-op form). Outputs un-double at the end.
//
// One block per batch element; each 16-lane group owns one LP (timestep);
// 4 gen slots/lane (g = 16*s + gl). Dead gens (g>=G) use poisoned constants
// (b=1e30, pmax=pmin=0) -> state pinned at 0.
//
// Pipeline: x^1 = relu(-tau*c) = 0 exactly -> free prologue. Iteration k
// (k = 1..nit-1): butterfly(xbar^{k-1}); gaps: per-gen dual update (y^k) and
// scalar-free primal part; then 2tau-scaled scalar rows; finish primal.
__global__ __launch_bounds__(512) void pdhg_fused_kernel(
    const float* __restrict__ forecast, const float* __restrict__ pminv,
    const float* __restrict__ pmaxv, const float* __restrict__ bv,
    const float* __restrict__ cv, const int* __restrict__ nitp,
    float* __restrict__ out, int G, int B, int T, float tau)
{
    __shared__ float sobj[64];
    const int bb   = blockIdx.x;
    const int w    = threadIdx.x >> 5;
    const int grp  = (threadIdx.x >> 4) & 1;
    const int gl   = threadIdx.x & 15;
    const int t    = 2 * w + grp;
    const bool live = t < T;
    const int tc   = live ? t : T - 1;
    const float D  = forecast[bb * T + tc];
    const int nit  = *nitp;
    const float sig = tau;
    const float nsig = -sig;
    const float ntau2 = -2.f * tau;           // primal row runs doubled
    const float tausig2  = 2.f * tau * sig;
    const float ntausig2 = -tausig2;
    const float sruD2 = tausig2 * (REQ_UP * D);
    const float srdD2 = tausig2 * (REQ_DN * D);

    float tb2[4], tcu2[4], tcd2[4], spx[4], spn[4];
#pragma unroll
    for (int s = 0; s < 4; ++s) {
        int g = 16 * s + gl;
        float bg = (g < G) ? bv[g]    : 1e30f;
        float px = (g < G) ? pmaxv[g] : 0.f;
        float pn = (g < G) ? pminv[g] : 0.f;
        tb2[s]  = 2.f * tau * bg;
        tcu2[s] = 2.f * tau * RES_UP * bg;
        tcd2[s] = 2.f * tau * RES_DN * bg;
        spx[s] = sig * px;
        spn[s] = sig * pn;
    }

    // state: DOUBLED primal X2 (P,Ru,Rd hold 2x), per-gen duals (normal),
    // 2tau-scaled scalar duals, carried xbar and carried lane partials.
    float P[4]  = {0,0,0,0}, Ru[4] = {0,0,0,0}, Rd[4] = {0,0,0,0};
    float av[4] = {0,0,0,0}, dv[4] = {0,0,0,0}, uv[4] = {0,0,0,0}, lv[4] = {0,0,0,0};
    float Pb[4] = {0,0,0,0}, Rub[4] = {0,0,0,0}, Rdb[4] = {0,0,0,0};
    float M = 0.f, WU = 0.f, WD = 0.f;   // -2tau*y0, 2tau*yu, 2tau*yd
    float sP = 0.f, sRu = 0.f, sRd = 0.f;

#pragma unroll 4
    for (int it = 1; it < nit; ++it) {
        float eP[4], eRu[4], eRd[4];

        // ---- butterfly stage 8 ----
        sP  += __shfl_xor_sync(0xffffffffu, sP,  8);
        sRu += __shfl_xor_sync(0xffffffffu, sRu, 8);
        sRd += __shfl_xor_sync(0xffffffffu, sRd, 8);
        // fill: a,d dual updates (both pairs) using xbar^{k-1}
#pragma unroll
        for (int q = 0; q < 2; ++q) {
            const int i = 2 * q, j = i + 1;
            float t0, t1, e0, e1;
            F2ADD(t0, t1, Pb[i], Pb[j], Rub[i], Rub[j]);
            F2SUB(e0, e1, av[i], av[j], spx[i], spx[j]);
            F2FMA(e0, e1, t0, t1, sig, sig, e0, e1);
            av[i] = fmaxf(e0, 0.f); av[j] = fmaxf(e1, 0.f);
            F2SUB(t0, t1, Rdb[i], Rdb[j], Pb[i], Pb[j]);
            F2ADD(e0, e1, dv[i], dv[j], spn[i], spn[j]);
            F2FMA(e0, e1, t0, t1, sig, sig, e0, e1);
            dv[i] = fmaxf(e0, 0.f); dv[j] = fmaxf(e1, 0.f);
        }

        // ---- butterfly stage 4 ----
        sP  += __shfl_xor_sync(0xffffffffu, sP,  4);
        sRu += __shfl_xor_sync(0xffffffffu, sRu, 4);
        sRd += __shfl_xor_sync(0xffffffffu, sRd, 4);
        // fill: u,l dual updates (both pairs)
#pragma unroll
        for (int q = 0; q < 2; ++q) {
            const int i = 2 * q, j = i + 1;
            float e0, e1;
            F2SUB(e0, e1, uv[i], uv[j], spx[i], spx[j]);
            F2FMA(e0, e1, Pb[i], Pb[j], sig, sig, e0, e1);
            uv[i] = fmaxf(e0, 0.f); uv[j] = fmaxf(e1, 0.f);
            F2ADD(e0, e1, lv[i], lv[j], spn[i], spn[j]);
            F2FMA(e0, e1, Pb[i], Pb[j], nsig, nsig, e0, e1);
            lv[i] = fmaxf(e0, 0.f); lv[j] = fmaxf(e1, 0.f);
        }

        // ---- butterfly stage 2 ----
        sP  += __shfl_xor_sync(0xffffffffu, sP,  2);
        sRu += __shfl_xor_sync(0xffffffffu, sRu, 2);
        sRd += __shfl_xor_sync(0xffffffffu, sRd, 2);
        // fill: scalar-free part of DOUBLED primal update (uses new duals y^k)
#pragma unroll
        for (int q = 0; q < 2; ++q) {
            const int i = 2 * q, j = i + 1;
            float t0, t1, s0, s1;
            F2SUB(t0, t1, av[i], av[j], dv[i], dv[j]);
            F2SUB(s0, s1, uv[i], uv[j], lv[i], lv[j]);
            F2ADD(t0, t1, t0, t1, s0, s1);
            F2SUB(eP[i], eP[j], P[i], P[j], tb2[i], tb2[j]);
            F2FMA(eP[i], eP[j], t0, t1, ntau2, ntau2, eP[i], eP[j]);
            F2SUB(eRu[i], eRu[j], Ru[i], Ru[j], tcu2[i], tcu2[j]);
            F2FMA(eRu[i], eRu[j], av[i], av[j], ntau2, ntau2, eRu[i], eRu[j]);
            F2SUB(eRd[i], eRd[j], Rd[i], Rd[j], tcd2[i], tcd2[j]);
            F2FMA(eRd[i], eRd[j], dv[i], dv[j], ntau2, ntau2, eRd[i], eRd[j]);
        }

        // ---- butterfly stage 1 ----
        sP  += __shfl_xor_sync(0xffffffffu, sP,  1);
        sRu += __shfl_xor_sync(0xffffffffu, sRu, 1);
        sRd += __shfl_xor_sync(0xffffffffu, sRd, 1);

        // 2tau-scaled scalar rows (y^k scalars)
        M  = fmaf(ntausig2, sP - D, M);
        WU = fmaxf(fmaf(ntausig2, sRu, WU + sruD2), 0.f);
        WD = fmaxf(fmaf(ntausig2, sRd, WD + srdD2), 0.f);

        // finish primal: add scalars, relu -> X2^{k+1};
        // xbar^k = fma(X2_old, -0.5, X2_new) in ONE op; lane partials.
#pragma unroll
        for (int q = 0; q < 2; ++q) {
            const int i = 2 * q, j = i + 1;
            float e0, e1;
            F2ADD(e0, e1, eP[i], eP[j], M, M);
            float Pn0 = fmaxf(e0, 0.f), Pn1 = fmaxf(e1, 0.f);
            F2ADD(e0, e1, eRu[i], eRu[j], WU, WU);
            float Run0 = fmaxf(e0, 0.f), Run1 = fmaxf(e1, 0.f);
            F2ADD(e0, e1, eRd[i], eRd[j], WD, WD);
            float Rdn0 = fmaxf(e0, 0.f), Rdn1 = fmaxf(e1, 0.f);
            F2FMA(Pb[i],  Pb[j],  P[i],  P[j],  -0.5f, -0.5f, Pn0,  Pn1);
            F2FMA(Rub[i], Rub[j], Ru[i], Ru[j], -0.5f, -0.5f, Run0, Run1);
            F2FMA(Rdb[i], Rdb[j], Rd[i], Rd[j], -0.5f, -0.5f, Rdn0, Rdn1);
            P[i] = Pn0; P[j] = Pn1; Ru[i] = Run0; Ru[j] = Run1; Rd[i] = Rdn0; Rd[j] = Rdn1;
        }
        {
            float h0, h1;
            F2ADD(h0, h1, Pb[0], Pb[1], Pb[2], Pb[3]);     sP  = h0 + h1;
            F2ADD(h0, h1, Rub[0], Rub[1], Rub[2], Rub[3]); sRu = h0 + h1;
            F2ADD(h0, h1, Rdb[0], Rdb[1], Rdb[2], Rdb[3]); sRd = h0 + h1;
        }
    }

    // outputs: P_DA | R_up | R_dn | obj | Cost_DA, all (B, G, T).
    // State is doubled -> multiply by 0.5 on the way out.
    size_t BGT = (size_t)B * G * T;
    float* Pout = out;
    float* Ruo  = out + BGT;
    float* Rdo  = out + 2 * BGT;
    float* Co   = out + 3 * BGT + B;

    float part = 0.f;
    if (live) {
#pragma unroll
        for (int s = 0; s < 4; ++s) {
            int g = 16 * s + gl;
            if (g < G) {
                size_t i = ((size_t)bb * G + g) * T + t;
                float bg = bv[g];
                float Ph  = 0.5f * P[s];
                float Ruh = 0.5f * Ru[s];
                float Rdh = 0.5f * Rd[s];
                float co = fmaf(bg, Ph, cv[g]);
                Pout[i] = Ph; Ruo[i] = Ruh; Rdo[i] = Rdh; Co[i] = co;
                part += co + RES_UP * bg * Ruh + RES_DN * bg * Rdh;
            }
        }
    }
#pragma unroll
    for (int k = 8; k > 0; k >>= 1)
        part += __shfl_xor_sync(0xffffffffu, part, k);
    if (live && gl == 0) sobj[t] = part;
    __syncthreads();

    // block reduction of T per-LP partials -> obj[bb] (warp 0 only)
    if (w == 0) {
        int lane = threadIdx.x & 31;
        float v = (lane < T) ? sobj[lane] : 0.f;
        if (32 + lane < T) v += sobj[32 + lane];
#pragma unroll
        for (int k = 16; k > 0; k >>= 1)
            v += __shfl_xor_sync(0xffffffffu, v, k);
        if (lane == 0) out[3 * BGT + bb] = v;
    }
}

// ---------------- host: structured spectral norm of K (power iteration) -----
static void K_matvec(const double* v, double* w, int G) {
    int n1 = G, n2 = 2 * G;
    double s0 = 0, s1 = 0, s2 = 0;
    for (int g = 0; g < G; ++g) { s0 += v[g]; s1 += v[n1 + g]; s2 += v[n2 + g]; }
    w[0] = s0;
    for (int g = 0; g < G; ++g) {
        w[1 + g]          =  v[g] + v[n1 + g];
        w[1 + G + g]      = -v[g] + v[n2 + g];
        w[1 + 2 * G + g]  =  v[g];
        w[1 + 3 * G + g]  = -v[g];
    }
    w[1 + 4 * G]     = -s1;
    w[1 + 4 * G + 1] = -s2;
}

static void KT_matvec(const double* w, double* z, int G) {
    double yu = w[1 + 4 * G], yd = w[1 + 4 * G + 1];
    for (int g = 0; g < G; ++g) {
        z[g]           = w[0] + w[1 + g] - w[1 + G + g] + w[1 + 2 * G + g] - w[1 + 3 * G + g];
        z[G + g]       = w[1 + g] - yu;
        z[2 * G + g]   = w[1 + G + g] - yd;
    }
}

static double spectral_norm_K(int G) {
    static double v[3 * MAXG], w[4 * MAXG + 3], z[3 * MAXG];
    int n = 3 * G;
    for (int i = 0; i < n; ++i) v[i] = 1.0 + 0.001 * (double)(i % 7);
    double lam = 1.0;
    for (int it = 0; it < 4000; ++it) {
        K_matvec(v, w, G);
        KT_matvec(w, z, G);
        double nrm = 0.0;
        for (int i = 0; i < n; ++i) nrm += z[i] * z[i];
        nrm = sqrt(nrm);
        lam = nrm;
        double inv = 1.0 / nrm;
        for (int i = 0; i < n; ++i) v[i] = z[i] * inv;
    }
    return sqrt(lam);  // sigma_max(K)
}

extern "C" void kernel_launch(void* const* d_in, const int* in_sizes, int n_in,
                              void* d_out, int out_size) {
    const float* forecast = (const float*)d_in[0];
    const float* pminv    = (const float*)d_in[1];
    const float* pmaxv    = (const float*)d_in[2];
    const float* bv       = (const float*)d_in[3];
    const float* cv       = (const float*)d_in[4];
    const int*   nitp     = (const int*)d_in[5];

    int G  = in_sizes[1];
    int BT = in_sizes[0];
    // out_size = 4*B*G*T + B  with  B*T = BT  ->  B = out_size - 4*G*BT
    int B = out_size - 4 * G * BT;
    if (B <= 0) B = 1;
    int T = BT / B;

    double L = spectral_norm_K(G);
    float tau = (float)(0.9 / L);

    float* out = (float*)d_out;
    int wpb = (T + 1) / 2;              // warps per block (one per 2 timesteps)
    if (wpb > 16) wpb = 16;             // safety: T <= 32 assumed for block fit
    pdhg_fused_kernel<<<B, wpb * 32>>>(
        forecast, pminv, pmaxv, bv, cv, nitp, out, G, B, T, tau);
}